// round 1
// baseline (speedup 1.0000x reference)
#include <cuda_runtime.h>

#define NN 100000
#define EE 1600000
#define GG 2048
#define DD 128
#define BN_EPS 1e-5f

// ---------------- scratch (static device globals; no allocs allowed) ----------------
__device__ float g_linS[NN * DD];   // dinv-scaled GEMM output
__device__ float g_h[NN * DD];      // post-activation features
__device__ int   g_row[EE];
__device__ int   g_col[EE];
__device__ int   g_batch[NN];
__device__ int   g_deg[NN];
__device__ float g_dinv[NN];
__device__ int   g_off[NN + 1];
__device__ int   g_cursor[NN];
__device__ int   g_csr[EE];
__device__ int   g_bsum[256];
__device__ float g_stats[2 * DD];   // [0:128) sum, [128:256) sumsq
__device__ float g_scale[DD];
__device__ float g_shift[DD];
__device__ float g_pool[GG * DD];
__device__ float g_cnt[GG];
__device__ int   g_is32;

__device__ __forceinline__ float lrelu(float x) { return x > 0.f ? x : 0.01f * x; }

// ---------------- setup kernels ----------------
__global__ void k_init() {
    int i = blockIdx.x * blockDim.x + threadIdx.x;
    if (i < NN) g_deg[i] = 0;
    if (i < GG * DD) g_pool[i] = 0.f;
    if (i < GG) g_cnt[i] = 0.f;
}

// Detect whether index buffers are int32 or int64. If int32 data is read as
// int64, pairs combine to values >= 2^32 (or negative) w.h.p.
__global__ void k_detect(const void* ei) {
    const long long* p = (const long long*)ei;
    __shared__ int bad;
    if (threadIdx.x == 0) bad = 0;
    __syncthreads();
    for (int i = threadIdx.x; i < 4096; i += blockDim.x) {
        long long v = p[i];
        if (v < 0 || v >= NN) bad = 1;
    }
    __syncthreads();
    if (threadIdx.x == 0) g_is32 = bad;
}

__global__ void k_convert(const void* ei, const void* bidx) {
    int e = blockIdx.x * blockDim.x + threadIdx.x;
    int is32 = g_is32;
    if (e < EE) {
        if (is32) {
            const int* p = (const int*)ei;
            g_row[e] = p[e];
            g_col[e] = p[EE + e];
        } else {
            const long long* p = (const long long*)ei;
            g_row[e] = (int)p[e];
            g_col[e] = (int)p[EE + e];
        }
    }
    if (e < NN) {
        if (is32) g_batch[e] = ((const int*)bidx)[e];
        else      g_batch[e] = (int)((const long long*)bidx)[e];
    }
}

__global__ void k_count() {
    int e = blockIdx.x * blockDim.x + threadIdx.x;
    if (e < EE) atomicAdd(&g_deg[g_col[e]], 1);
}

__global__ void k_dinv() {
    int i = blockIdx.x * blockDim.x + threadIdx.x;
    if (i < NN) g_dinv[i] = rsqrtf((float)g_deg[i] + 1.0f);
}

__global__ void k_cntnodes() {
    int i = blockIdx.x * blockDim.x + threadIdx.x;
    if (i < NN) atomicAdd(&g_cnt[g_batch[i]], 1.0f);
}

// ---------------- exclusive scan of deg -> off (3 kernels, 256 blocks x 512 elems) ----------------
__global__ void k_scanA() {
    __shared__ int s[256];
    int b = blockIdx.x, t = threadIdx.x;
    int base = b * 512 + t * 2;
    int v0 = (base < NN) ? g_deg[base] : 0;
    int v1 = (base + 1 < NN) ? g_deg[base + 1] : 0;
    int tsum = v0 + v1;
    s[t] = tsum;
    __syncthreads();
    int val = tsum;
    for (int d = 1; d < 256; d <<= 1) {
        int o = (t >= d) ? s[t - d] : 0;
        __syncthreads();
        val += o;
        s[t] = val;
        __syncthreads();
    }
    int excl = val - tsum;
    if (base < NN) g_off[base] = excl;
    if (base + 1 < NN) g_off[base + 1] = excl + v0;
    if (t == 255) g_bsum[b] = val;
}

__global__ void k_scanB() {
    __shared__ int s[256];
    int t = threadIdx.x;
    int v = g_bsum[t];
    s[t] = v;
    __syncthreads();
    int val = v;
    for (int d = 1; d < 256; d <<= 1) {
        int o = (t >= d) ? s[t - d] : 0;
        __syncthreads();
        val += o;
        s[t] = val;
        __syncthreads();
    }
    g_bsum[t] = val - v;
}

__global__ void k_scanC() {
    int i = blockIdx.x * blockDim.x + threadIdx.x;
    if (i < NN) {
        int o = g_off[i] + g_bsum[i >> 9];
        g_off[i] = o;
        g_cursor[i] = o;
    }
    if (i == 0) g_off[NN] = EE;
}

__global__ void k_scatter() {
    int e = blockIdx.x * blockDim.x + threadIdx.x;
    if (e < EE) {
        int c = g_col[e];
        int slot = atomicAdd(&g_cursor[c], 1);
        g_csr[slot] = g_row[e];
    }
}

__global__ void k_zero_stats() {
    int i = threadIdx.x;
    if (i < 2 * DD) g_stats[i] = 0.f;
}

// ---------------- layer 0 GEMM: linS = dinv * (x[N,9] @ W0[9,128]) ----------------
__global__ void __launch_bounds__(256) k_gemm0(const float* __restrict__ x,
                                               const float* __restrict__ W0) {
    __shared__ float Ws[9 * DD];
    for (int i = threadIdx.x; i < 9 * DD; i += blockDim.x) Ws[i] = W0[i];
    __syncthreads();
    int gid = blockIdx.x * blockDim.x + threadIdx.x;
    if (gid >= NN * DD) return;
    int i = gid >> 7, f = gid & 127;
    float s = 0.f;
#pragma unroll
    for (int k = 0; k < 9; k++) s += x[i * 9 + k] * Ws[k * DD + f];
    g_linS[gid] = g_dinv[i] * s;
}

// ---------------- main GEMM: linS = dinv * (BN(h) @ W), BN folded into A-load ----------------
__global__ void __launch_bounds__(256) k_gemm128(const float* __restrict__ W) {
    __shared__ float As[16][DD + 4];
    __shared__ float Bs[16][DD];
    int row0 = blockIdx.x * 128;
    int tid = threadIdx.x;
    int tr = tid >> 4, tc = tid & 15;
    float acc[8][8];
#pragma unroll
    for (int m = 0; m < 8; m++)
#pragma unroll
        for (int n = 0; n < 8; n++) acc[m][n] = 0.f;

    const float4* A4 = (const float4*)g_h;
    const float4* W4 = (const float4*)W;

    for (int k0 = 0; k0 < DD; k0 += 16) {
        // A tile: 128 rows x 16 k, BN scale/shift applied per-feature
#pragma unroll
        for (int q = 0; q < 2; q++) {
            int slot = tid * 2 + q;          // 0..511
            int r = slot >> 2;               // 0..127
            int kq = slot & 3;               // 0..3 (float4 within 16 k)
            int grow = row0 + r;
            float4 v = make_float4(0.f, 0.f, 0.f, 0.f);
            if (grow < NN) v = A4[grow * 32 + (k0 >> 2) + kq];
            int kk = kq * 4;
            As[kk + 0][r] = v.x * g_scale[k0 + kk + 0] + g_shift[k0 + kk + 0];
            As[kk + 1][r] = v.y * g_scale[k0 + kk + 1] + g_shift[k0 + kk + 1];
            As[kk + 2][r] = v.z * g_scale[k0 + kk + 2] + g_shift[k0 + kk + 2];
            As[kk + 3][r] = v.w * g_scale[k0 + kk + 3] + g_shift[k0 + kk + 3];
        }
        // B tile: 16 k x 128 n
#pragma unroll
        for (int q = 0; q < 2; q++) {
            int slot = tid * 2 + q;          // 0..511
            int kk = slot >> 5;              // 0..15
            int n4 = slot & 31;              // float4 column
            float4 v = W4[(k0 + kk) * 32 + n4];
            ((float4*)&Bs[kk][0])[n4] = v;
        }
        __syncthreads();
#pragma unroll
        for (int kk = 0; kk < 16; kk++) {
            float4 a0 = *(const float4*)&As[kk][tr * 8];
            float4 a1 = *(const float4*)&As[kk][tr * 8 + 4];
            float4 b0 = *(const float4*)&Bs[kk][tc * 8];
            float4 b1 = *(const float4*)&Bs[kk][tc * 8 + 4];
            float a[8] = {a0.x, a0.y, a0.z, a0.w, a1.x, a1.y, a1.z, a1.w};
            float bb[8] = {b0.x, b0.y, b0.z, b0.w, b1.x, b1.y, b1.z, b1.w};
#pragma unroll
            for (int m = 0; m < 8; m++)
#pragma unroll
                for (int n = 0; n < 8; n++) acc[m][n] += a[m] * bb[n];
        }
        __syncthreads();
    }

    float4* out4 = (float4*)g_linS;
#pragma unroll
    for (int m = 0; m < 8; m++) {
        int row = row0 + tr * 8 + m;
        if (row < NN) {
            float d = g_dinv[row];
            float4 o0 = make_float4(d * acc[m][0], d * acc[m][1], d * acc[m][2], d * acc[m][3]);
            float4 o1 = make_float4(d * acc[m][4], d * acc[m][5], d * acc[m][6], d * acc[m][7]);
            out4[row * 32 + tc * 2 + 0] = o0;
            out4[row * 32 + tc * 2 + 1] = o1;
        }
    }
}

// ---------------- SpMM: warp per destination node ----------------
template <bool FINAL>
__global__ void __launch_bounds__(256) k_spmm(const float* __restrict__ bias) {
    __shared__ float ssum[DD], ssq[DD];
    int tid = threadIdx.x;
    if (!FINAL) {
        for (int i = tid; i < DD; i += blockDim.x) { ssum[i] = 0.f; ssq[i] = 0.f; }
        __syncthreads();
    }
    int lane = tid & 31;
    int gw = (blockIdx.x * blockDim.x + tid) >> 5;
    int nw = (gridDim.x * blockDim.x) >> 5;
    const float4* lin4 = (const float4*)g_linS;
    float4 b4 = ((const float4*)bias)[lane];
    float s0 = 0, s1 = 0, s2 = 0, s3 = 0, q0 = 0, q1 = 0, q2 = 0, q3 = 0;

    for (int i = gw; i < NN; i += nw) {
        int e0 = g_off[i], e1 = g_off[i + 1];
        float ax = 0, ay = 0, az = 0, aw = 0;
        int e = e0;
        for (; e + 4 <= e1; e += 4) {
            int r0 = g_csr[e], r1 = g_csr[e + 1], r2 = g_csr[e + 2], r3 = g_csr[e + 3];
            float4 v0 = lin4[r0 * 32 + lane];
            float4 v1 = lin4[r1 * 32 + lane];
            float4 v2 = lin4[r2 * 32 + lane];
            float4 v3 = lin4[r3 * 32 + lane];
            ax += (v0.x + v1.x) + (v2.x + v3.x);
            ay += (v0.y + v1.y) + (v2.y + v3.y);
            az += (v0.z + v1.z) + (v2.z + v3.z);
            aw += (v0.w + v1.w) + (v2.w + v3.w);
        }
        for (; e < e1; e++) {
            int r = g_csr[e];
            float4 v = lin4[r * 32 + lane];
            ax += v.x; ay += v.y; az += v.z; aw += v.w;
        }
        float4 self = lin4[i * 32 + lane];
        float di = g_dinv[i];
        float hx = lrelu(di * (ax + self.x) + b4.x);
        float hy = lrelu(di * (ay + self.y) + b4.y);
        float hz = lrelu(di * (az + self.z) + b4.z);
        float hw = lrelu(di * (aw + self.w) + b4.w);
        if (!FINAL) {
            ((float4*)g_h)[i * 32 + lane] = make_float4(hx, hy, hz, hw);
            s0 += hx; s1 += hy; s2 += hz; s3 += hw;
            q0 += hx * hx; q1 += hy * hy; q2 += hz * hz; q3 += hw * hw;
        } else {
            int bi = g_batch[i];
            float* p = &g_pool[bi * DD + lane * 4];
            atomicAdd(p + 0, hx);
            atomicAdd(p + 1, hy);
            atomicAdd(p + 2, hz);
            atomicAdd(p + 3, hw);
        }
    }

    if (!FINAL) {
        atomicAdd(&ssum[lane * 4 + 0], s0);
        atomicAdd(&ssum[lane * 4 + 1], s1);
        atomicAdd(&ssum[lane * 4 + 2], s2);
        atomicAdd(&ssum[lane * 4 + 3], s3);
        atomicAdd(&ssq[lane * 4 + 0], q0);
        atomicAdd(&ssq[lane * 4 + 1], q1);
        atomicAdd(&ssq[lane * 4 + 2], q2);
        atomicAdd(&ssq[lane * 4 + 3], q3);
        __syncthreads();
        for (int i = tid; i < DD; i += blockDim.x) {
            atomicAdd(&g_stats[i], ssum[i]);
            atomicAdd(&g_stats[DD + i], ssq[i]);
        }
    }
}

__global__ void k_bnprep(const float* __restrict__ gam, const float* __restrict__ bet) {
    int f = threadIdx.x;
    if (f < DD) {
        float m = g_stats[f] * (1.0f / NN);
        float v = g_stats[DD + f] * (1.0f / NN) - m * m;
        float sc = gam[f] * rsqrtf(fmaxf(v, 0.f) + BN_EPS);
        g_scale[f] = sc;
        g_shift[f] = bet[f] - m * sc;
    }
}

// ---------------- output head: warp per graph ----------------
__global__ void k_out(const float* __restrict__ Wout, const float* __restrict__ bout,
                      float* __restrict__ out) {
    int t = blockIdx.x * blockDim.x + threadIdx.x;
    int w = t >> 5, lane = t & 31;
    if (w >= GG) return;
    float4 p = ((const float4*)g_pool)[w * 32 + lane];
    float4 wv = ((const float4*)Wout)[lane];
    float d = p.x * wv.x + p.y * wv.y + p.z * wv.z + p.w * wv.w;
#pragma unroll
    for (int o = 16; o; o >>= 1) d += __shfl_down_sync(0xffffffffu, d, o);
    if (lane == 0) {
        float c = fmaxf(g_cnt[w], 1.0f);
        out[w] = d / c + bout[0];
    }
}

// ---------------- launch ----------------
extern "C" void kernel_launch(void* const* d_in, const int* in_sizes, int n_in,
                              void* d_out, int out_size) {
    const float* x     = (const float*)d_in[0];
    const void*  ei    = d_in[1];
    const void*  bidx  = d_in[2];
    const float* W0    = (const float*)d_in[3];
    const float* b0    = (const float*)d_in[4];
    const float* W1    = (const float*)d_in[5];
    const float* b1    = (const float*)d_in[6];
    const float* W2    = (const float*)d_in[7];
    const float* b2    = (const float*)d_in[8];
    const float* W3    = (const float*)d_in[9];
    const float* b3    = (const float*)d_in[10];
    const float* g1    = (const float*)d_in[11];
    const float* be1   = (const float*)d_in[12];
    const float* g2    = (const float*)d_in[13];
    const float* be2   = (const float*)d_in[14];
    const float* g3    = (const float*)d_in[15];
    const float* be3   = (const float*)d_in[16];
    const float* Wout  = (const float*)d_in[17];
    const float* bout  = (const float*)d_in[18];
    float* out = (float*)d_out;

    const int EB = (EE + 255) / 256;     // 6250
    const int NB = (NN + 255) / 256;     // 391
    const int SPMM_BLOCKS = 888;         // grid-stride, warp per node

    // preprocessing
    k_init<<<(GG * DD + 255) / 256, 256>>>();
    k_detect<<<1, 256>>>(ei);
    k_convert<<<EB, 256>>>(ei, bidx);
    k_count<<<EB, 256>>>();
    k_dinv<<<NB, 256>>>();
    k_scanA<<<256, 256>>>();
    k_scanB<<<1, 256>>>();
    k_scanC<<<NB, 256>>>();
    k_scatter<<<EB, 256>>>();
    k_cntnodes<<<NB, 256>>>();

    // layer 0 (K=9)
    k_gemm0<<<(NN * DD) / 256, 256>>>(x, W0);
    k_zero_stats<<<1, 256>>>();
    k_spmm<false><<<SPMM_BLOCKS, 256>>>(b0);

    // layer 1
    k_bnprep<<<1, 128>>>(g1, be1);
    k_gemm128<<<(NN + 127) / 128, 256>>>(W1);
    k_zero_stats<<<1, 256>>>();
    k_spmm<false><<<SPMM_BLOCKS, 256>>>(b1);

    // layer 2
    k_bnprep<<<1, 128>>>(g2, be2);
    k_gemm128<<<(NN + 127) / 128, 256>>>(W2);
    k_zero_stats<<<1, 256>>>();
    k_spmm<false><<<SPMM_BLOCKS, 256>>>(b2);

    // layer 3 (final, fused pooling)
    k_bnprep<<<1, 128>>>(g3, be3);
    k_gemm128<<<(NN + 127) / 128, 256>>>(W3);
    k_spmm<true><<<SPMM_BLOCKS, 256>>>(b3);

    // head
    k_out<<<(GG * 32 + 255) / 256, 256>>>(Wout, bout, out);

    (void)in_sizes; (void)n_in; (void)out_size;
}

// round 2
// speedup vs baseline: 1.0723x; 1.0723x over previous
#include <cuda_runtime.h>

#define NN 100000
#define EE 1600000
#define GG 2048
#define DD 128
#define BN_EPS 1e-5f

// ---------------- packed f32x2 PTX helpers ----------------
#define FFMA2(c, a, b) asm("fma.rn.f32x2 %0, %1, %2, %0;" : "+l"(c) : "l"(a), "l"(b))
#define FADD2(c, b)    asm("add.rn.f32x2 %0, %0, %1;"     : "+l"(c) : "l"(b))
#define PACK2(o, lo, hi) asm("mov.b64 %0, {%1, %2};" : "=l"(o) : "f"(lo), "f"(hi))
#define UNPACK2(lo, hi, i) asm("mov.b64 {%0, %1}, %2;" : "=f"(lo), "=f"(hi) : "l"(i))

// ---------------- scratch (static device globals; no allocs allowed) ----------------
__device__ float g_linS[NN * DD];   // dinv-scaled GEMM output
__device__ float g_h[NN * DD];      // post-activation features
__device__ int   g_row[EE];
__device__ int   g_col[EE];
__device__ int   g_batch[NN];
__device__ int   g_deg[NN];
__device__ float g_dinv[NN];
__device__ int   g_off[NN + 1];
__device__ int   g_cursor[NN];
__device__ int   g_csr[EE];
__device__ int   g_bsum[256];
__device__ float g_stats[2 * DD];   // [0:128) sum, [128:256) sumsq
__device__ float g_scale[DD];
__device__ float g_shift[DD];
__device__ float g_Wp[DD * DD];     // scale-folded weights
__device__ float g_rvec[DD];        // shift @ W
__device__ float g_pool[GG * DD];
__device__ float g_cnt[GG];
__device__ int   g_is32;

__device__ __forceinline__ float lrelu(float x) { return x > 0.f ? x : 0.01f * x; }

// ---------------- setup kernels ----------------
__global__ void k_init() {
    int i = blockIdx.x * blockDim.x + threadIdx.x;
    if (i < NN) g_deg[i] = 0;
    if (i < GG * DD) g_pool[i] = 0.f;
    if (i < GG) g_cnt[i] = 0.f;
    if (i < 2 * DD) g_stats[i] = 0.f;
}

// Detect whether index buffers are int32 or int64.
__global__ void k_detect(const void* ei) {
    const long long* p = (const long long*)ei;
    __shared__ int bad;
    if (threadIdx.x == 0) bad = 0;
    __syncthreads();
    for (int i = threadIdx.x; i < 4096; i += blockDim.x) {
        long long v = p[i];
        if (v < 0 || v >= NN) bad = 1;
    }
    __syncthreads();
    if (threadIdx.x == 0) g_is32 = bad;
}

// convert indices + degree histogram + batch convert + graph-size histogram
__global__ void k_convert_all(const void* ei, const void* bidx) {
    int e = blockIdx.x * blockDim.x + threadIdx.x;
    int is32 = g_is32;
    if (e < EE) {
        int r, c;
        if (is32) {
            const int* p = (const int*)ei;
            r = p[e]; c = p[EE + e];
        } else {
            const long long* p = (const long long*)ei;
            r = (int)p[e]; c = (int)p[EE + e];
        }
        g_row[e] = r;
        g_col[e] = c;
        atomicAdd(&g_deg[c], 1);
    }
    if (e < NN) {
        int b = is32 ? ((const int*)bidx)[e] : (int)((const long long*)bidx)[e];
        g_batch[e] = b;
        atomicAdd(&g_cnt[b], 1.0f);
    }
}

__global__ void k_dinv() {
    int i = blockIdx.x * blockDim.x + threadIdx.x;
    if (i < NN) g_dinv[i] = rsqrtf((float)g_deg[i] + 1.0f);
}

// ---------------- exclusive scan of deg -> off ----------------
__global__ void k_scanA() {
    __shared__ int s[256];
    int b = blockIdx.x, t = threadIdx.x;
    int base = b * 512 + t * 2;
    int v0 = (base < NN) ? g_deg[base] : 0;
    int v1 = (base + 1 < NN) ? g_deg[base + 1] : 0;
    int tsum = v0 + v1;
    s[t] = tsum;
    __syncthreads();
    int val = tsum;
    for (int d = 1; d < 256; d <<= 1) {
        int o = (t >= d) ? s[t - d] : 0;
        __syncthreads();
        val += o;
        s[t] = val;
        __syncthreads();
    }
    int excl = val - tsum;
    if (base < NN) g_off[base] = excl;
    if (base + 1 < NN) g_off[base + 1] = excl + v0;
    if (t == 255) g_bsum[b] = val;
}

__global__ void k_scanB() {
    __shared__ int s[256];
    int t = threadIdx.x;
    int v = g_bsum[t];
    s[t] = v;
    __syncthreads();
    int val = v;
    for (int d = 1; d < 256; d <<= 1) {
        int o = (t >= d) ? s[t - d] : 0;
        __syncthreads();
        val += o;
        s[t] = val;
        __syncthreads();
    }
    g_bsum[t] = val - v;
}

__global__ void k_scanC() {
    int i = blockIdx.x * blockDim.x + threadIdx.x;
    if (i < NN) {
        int o = g_off[i] + g_bsum[i >> 9];
        g_off[i] = o;
        g_cursor[i] = o;
    }
    if (i == 0) g_off[NN] = EE;
}

__global__ void k_scatter() {
    int e = blockIdx.x * blockDim.x + threadIdx.x;
    if (e < EE) {
        int c = g_col[e];
        int slot = atomicAdd(&g_cursor[c], 1);
        g_csr[slot] = g_row[e];
    }
}

// ---------------- layer 0 GEMM: linS = dinv * (x[N,9] @ W0[9,128]) ----------------
__global__ void __launch_bounds__(256) k_gemm0(const float* __restrict__ x,
                                               const float* __restrict__ W0) {
    __shared__ float Ws[9 * DD];
    for (int i = threadIdx.x; i < 9 * DD; i += blockDim.x) Ws[i] = W0[i];
    __syncthreads();
    int gid = blockIdx.x * blockDim.x + threadIdx.x;
    if (gid >= NN * DD) return;
    int i = gid >> 7, f = gid & 127;
    float s = 0.f;
#pragma unroll
    for (int k = 0; k < 9; k++) s += x[i * 9 + k] * Ws[k * DD + f];
    g_linS[gid] = g_dinv[i] * s;
}

// ---------------- BN prep: stats -> scale/shift, then reset stats ----------------
__global__ void k_bnprep(const float* __restrict__ gam, const float* __restrict__ bet) {
    int f = threadIdx.x;
    if (f < DD) {
        float m = g_stats[f] * (1.0f / NN);
        float v = g_stats[DD + f] * (1.0f / NN) - m * m;
        float sc = gam[f] * rsqrtf(fmaxf(v, 0.f) + BN_EPS);
        g_scale[f] = sc;
        g_shift[f] = bet[f] - m * sc;
        g_stats[f] = 0.f;
        g_stats[DD + f] = 0.f;
    }
}

// ---------------- weight prep: Wp = diag(scale) W ; rvec = shift @ W ----------------
__global__ void __launch_bounds__(256) k_wprep(const float* __restrict__ W) {
    if (blockIdx.x < 64) {
        int idx = blockIdx.x * 256 + threadIdx.x;     // 0..16383
        int k = idx >> 7;
        g_Wp[idx] = g_scale[k] * W[idx];
    } else {
        int n = threadIdx.x;
        if (n < DD) {
            float s = 0.f;
#pragma unroll 8
            for (int k = 0; k < DD; k++) s += g_shift[k] * W[k * DD + n];
            g_rvec[n] = s;
        }
    }
}

// ---------------- main GEMM: linS = dinv * (h @ Wp + rvec), f32x2 microkernel ----------------
__global__ void __launch_bounds__(256) k_gemm128() {
    __shared__ float As[2][16][132];
    __shared__ float Bs[2][16][128];
    int row0 = blockIdx.x * 128;
    int tid = threadIdx.x;
    int tr = tid >> 4, tc = tid & 15;

    unsigned long long acc2[8][4] = {};    // 8 m-rows x 4 n-pairs

    const float4* A4 = (const float4*)g_h;
    const float4* W4 = (const float4*)g_Wp;

    // load-reg staging
    float4 la0, la1, lb0, lb1;
    int slot0 = tid * 2, slot1 = tid * 2 + 1;
    int ar0 = slot0 >> 2, akq0 = slot0 & 3;
    int ar1 = slot1 >> 2, akq1 = slot1 & 3;
    int bk0 = slot0 >> 5, bn0 = slot0 & 31;
    int bk1 = slot1 >> 5, bn1 = slot1 & 31;
    int grow0 = row0 + ar0, grow1 = row0 + ar1;
    bool ok0 = grow0 < NN, ok1 = grow1 < NN;

#define LOADREGS(kt)                                                        \
    {                                                                       \
        la0 = ok0 ? A4[grow0 * 32 + (kt) * 4 + akq0]                        \
                  : make_float4(0.f, 0.f, 0.f, 0.f);                        \
        la1 = ok1 ? A4[grow1 * 32 + (kt) * 4 + akq1]                        \
                  : make_float4(0.f, 0.f, 0.f, 0.f);                        \
        lb0 = W4[((kt) * 16 + bk0) * 32 + bn0];                             \
        lb1 = W4[((kt) * 16 + bk1) * 32 + bn1];                             \
    }

#define STORESMEM(buf)                                                      \
    {                                                                       \
        As[buf][akq0 * 4 + 0][ar0] = la0.x;                                 \
        As[buf][akq0 * 4 + 1][ar0] = la0.y;                                 \
        As[buf][akq0 * 4 + 2][ar0] = la0.z;                                 \
        As[buf][akq0 * 4 + 3][ar0] = la0.w;                                 \
        As[buf][akq1 * 4 + 0][ar1] = la1.x;                                 \
        As[buf][akq1 * 4 + 1][ar1] = la1.y;                                 \
        As[buf][akq1 * 4 + 2][ar1] = la1.z;                                 \
        As[buf][akq1 * 4 + 3][ar1] = la1.w;                                 \
        *(float4*)&Bs[buf][bk0][bn0 * 4] = lb0;                             \
        *(float4*)&Bs[buf][bk1][bn1 * 4] = lb1;                             \
    }

    LOADREGS(0);
    STORESMEM(0);
    __syncthreads();

    for (int kt = 0; kt < 8; kt++) {
        int buf = kt & 1;
        if (kt < 7) LOADREGS(kt + 1);
#pragma unroll
        for (int kk = 0; kk < 16; kk++) {
            float4 a0 = *(const float4*)&As[buf][kk][tr * 8];
            float4 a1 = *(const float4*)&As[buf][kk][tr * 8 + 4];
            ulonglong2 bb0 = *(const ulonglong2*)&Bs[buf][kk][tc * 8];
            ulonglong2 bb1 = *(const ulonglong2*)&Bs[buf][kk][tc * 8 + 4];
            unsigned long long bp0 = bb0.x, bp1 = bb0.y, bp2 = bb1.x, bp3 = bb1.y;
            float av[8] = {a0.x, a0.y, a0.z, a0.w, a1.x, a1.y, a1.z, a1.w};
#pragma unroll
            for (int m = 0; m < 8; m++) {
                unsigned long long am2;
                PACK2(am2, av[m], av[m]);
                FFMA2(acc2[m][0], am2, bp0);
                FFMA2(acc2[m][1], am2, bp1);
                FFMA2(acc2[m][2], am2, bp2);
                FFMA2(acc2[m][3], am2, bp3);
            }
        }
        if (kt < 7) STORESMEM((kt + 1) & 1);
        __syncthreads();
    }
#undef LOADREGS
#undef STORESMEM

    // epilogue: out = dinv * (acc + rvec)
    const float* rv = &g_rvec[tc * 8];
    float r0 = rv[0], r1 = rv[1], r2 = rv[2], r3 = rv[3];
    float r4 = rv[4], r5 = rv[5], r6 = rv[6], r7 = rv[7];
    float4* out4 = (float4*)g_linS;
#pragma unroll
    for (int m = 0; m < 8; m++) {
        int row = row0 + tr * 8 + m;
        if (row < NN) {
            float d = g_dinv[row];
            float c0, c1, c2, c3, c4, c5, c6, c7;
            UNPACK2(c0, c1, acc2[m][0]);
            UNPACK2(c2, c3, acc2[m][1]);
            UNPACK2(c4, c5, acc2[m][2]);
            UNPACK2(c6, c7, acc2[m][3]);
            float4 o0 = make_float4(d * (c0 + r0), d * (c1 + r1),
                                    d * (c2 + r2), d * (c3 + r3));
            float4 o1 = make_float4(d * (c4 + r4), d * (c5 + r5),
                                    d * (c6 + r6), d * (c7 + r7));
            out4[row * 32 + tc * 2 + 0] = o0;
            out4[row * 32 + tc * 2 + 1] = o1;
        }
    }
}

// ---------------- SpMM: warp per destination node, packed adds ----------------
template <bool FINAL>
__global__ void __launch_bounds__(256) k_spmm(const float* __restrict__ bias) {
    __shared__ float ssum[DD], ssq[DD];
    int tid = threadIdx.x;
    if (!FINAL) {
        for (int i = tid; i < DD; i += blockDim.x) { ssum[i] = 0.f; ssq[i] = 0.f; }
        __syncthreads();
    }
    int lane = tid & 31;
    int gw = (blockIdx.x * blockDim.x + tid) >> 5;
    int nw = (gridDim.x * blockDim.x) >> 5;
    const ulonglong2* lin2 = (const ulonglong2*)g_linS;
    ulonglong2 b2 = ((const ulonglong2*)bias)[lane];
    float s0 = 0, s1 = 0, s2 = 0, s3 = 0, q0 = 0, q1 = 0, q2 = 0, q3 = 0;

    for (int i = gw; i < NN; i += nw) {
        int e0 = g_off[i], e1 = g_off[i + 1];
        unsigned long long A0 = 0ull, A1 = 0ull;   // (0f,0f) packed
        int e = e0;
        for (; e + 4 <= e1; e += 4) {
            int r0 = g_csr[e], r1 = g_csr[e + 1], r2 = g_csr[e + 2], r3 = g_csr[e + 3];
            ulonglong2 v0 = lin2[r0 * 32 + lane];
            ulonglong2 v1 = lin2[r1 * 32 + lane];
            ulonglong2 v2 = lin2[r2 * 32 + lane];
            ulonglong2 v3 = lin2[r3 * 32 + lane];
            FADD2(A0, v0.x); FADD2(A1, v0.y);
            FADD2(A0, v1.x); FADD2(A1, v1.y);
            FADD2(A0, v2.x); FADD2(A1, v2.y);
            FADD2(A0, v3.x); FADD2(A1, v3.y);
        }
        for (; e < e1; e++) {
            int r = g_csr[e];
            ulonglong2 v = lin2[r * 32 + lane];
            FADD2(A0, v.x); FADD2(A1, v.y);
        }
        ulonglong2 self = lin2[i * 32 + lane];
        FADD2(A0, self.x); FADD2(A1, self.y);
        float di = g_dinv[i];
        unsigned long long d2;
        PACK2(d2, di, di);
        unsigned long long H0 = b2.x, H1 = b2.y;
        FFMA2(H0, d2, A0);
        FFMA2(H1, d2, A1);
        float hx, hy, hz, hw;
        UNPACK2(hx, hy, H0);
        UNPACK2(hz, hw, H1);
        hx = lrelu(hx); hy = lrelu(hy); hz = lrelu(hz); hw = lrelu(hw);
        if (!FINAL) {
            ((float4*)g_h)[i * 32 + lane] = make_float4(hx, hy, hz, hw);
            s0 += hx; s1 += hy; s2 += hz; s3 += hw;
            q0 += hx * hx; q1 += hy * hy; q2 += hz * hz; q3 += hw * hw;
        } else {
            int bi = g_batch[i];
            float* p = &g_pool[bi * DD + lane * 4];
            atomicAdd(p + 0, hx);
            atomicAdd(p + 1, hy);
            atomicAdd(p + 2, hz);
            atomicAdd(p + 3, hw);
        }
    }

    if (!FINAL) {
        atomicAdd(&ssum[lane * 4 + 0], s0);
        atomicAdd(&ssum[lane * 4 + 1], s1);
        atomicAdd(&ssum[lane * 4 + 2], s2);
        atomicAdd(&ssum[lane * 4 + 3], s3);
        atomicAdd(&ssq[lane * 4 + 0], q0);
        atomicAdd(&ssq[lane * 4 + 1], q1);
        atomicAdd(&ssq[lane * 4 + 2], q2);
        atomicAdd(&ssq[lane * 4 + 3], q3);
        __syncthreads();
        for (int i = tid; i < DD; i += blockDim.x) {
            atomicAdd(&g_stats[i], ssum[i]);
            atomicAdd(&g_stats[DD + i], ssq[i]);
        }
    }
}

// ---------------- output head: warp per graph ----------------
__global__ void k_out(const float* __restrict__ Wout, const float* __restrict__ bout,
                      float* __restrict__ out) {
    int t = blockIdx.x * blockDim.x + threadIdx.x;
    int w = t >> 5, lane = t & 31;
    if (w >= GG) return;
    float4 p = ((const float4*)g_pool)[w * 32 + lane];
    float4 wv = ((const float4*)Wout)[lane];
    float d = p.x * wv.x + p.y * wv.y + p.z * wv.z + p.w * wv.w;
#pragma unroll
    for (int o = 16; o; o >>= 1) d += __shfl_down_sync(0xffffffffu, d, o);
    if (lane == 0) {
        float c = fmaxf(g_cnt[w], 1.0f);
        out[w] = d / c + bout[0];
    }
}

// ---------------- launch ----------------
extern "C" void kernel_launch(void* const* d_in, const int* in_sizes, int n_in,
                              void* d_out, int out_size) {
    const float* x     = (const float*)d_in[0];
    const void*  ei    = d_in[1];
    const void*  bidx  = d_in[2];
    const float* W0    = (const float*)d_in[3];
    const float* b0    = (const float*)d_in[4];
    const float* W1    = (const float*)d_in[5];
    const float* b1    = (const float*)d_in[6];
    const float* W2    = (const float*)d_in[7];
    const float* b2    = (const float*)d_in[8];
    const float* W3    = (const float*)d_in[9];
    const float* b3    = (const float*)d_in[10];
    const float* g1    = (const float*)d_in[11];
    const float* be1   = (const float*)d_in[12];
    const float* g2    = (const float*)d_in[13];
    const float* be2   = (const float*)d_in[14];
    const float* g3    = (const float*)d_in[15];
    const float* be3   = (const float*)d_in[16];
    const float* Wout  = (const float*)d_in[17];
    const float* bout  = (const float*)d_in[18];
    float* out = (float*)d_out;

    const int EB = (EE + 255) / 256;     // 6250
    const int NB = (NN + 255) / 256;     // 391
    const int GB = (NN + 127) / 128;     // 782
    const int SPMM_BLOCKS = 888;

    // preprocessing
    k_init<<<(GG * DD + 255) / 256, 256>>>();
    k_detect<<<1, 256>>>(ei);
    k_convert_all<<<EB, 256>>>(ei, bidx);
    k_dinv<<<NB, 256>>>();
    k_scanA<<<256, 256>>>();
    k_scanB<<<1, 256>>>();
    k_scanC<<<NB, 256>>>();
    k_scatter<<<EB, 256>>>();

    // layer 0 (K=9)
    k_gemm0<<<(NN * DD) / 256, 256>>>(x, W0);
    k_spmm<false><<<SPMM_BLOCKS, 256>>>(b0);

    // layer 1
    k_bnprep<<<1, 128>>>(g1, be1);
    k_wprep<<<65, 256>>>(W1);
    k_gemm128<<<GB, 256>>>();
    k_spmm<false><<<SPMM_BLOCKS, 256>>>(b1);

    // layer 2
    k_bnprep<<<1, 128>>>(g2, be2);
    k_wprep<<<65, 256>>>(W2);
    k_gemm128<<<GB, 256>>>();
    k_spmm<false><<<SPMM_BLOCKS, 256>>>(b2);

    // layer 3 (final, fused pooling)
    k_bnprep<<<1, 128>>>(g3, be3);
    k_wprep<<<65, 256>>>(W3);
    k_gemm128<<<GB, 256>>>();
    k_spmm<true><<<SPMM_BLOCKS, 256>>>(b3);

    // head
    k_out<<<(GG * 32 + 255) / 256, 256>>>(Wout, bout, out);

    (void)in_sizes; (void)n_in; (void)out_size;
}

// round 4
// speedup vs baseline: 1.1794x; 1.0998x over previous
#include <cuda_runtime.h>
#include <cuda_fp16.h>

#define NN 100000
#define EE 1600000
#define GG 2048
#define DD 128
#define BN_EPS 1e-5f

// ---------------- packed f32x2 PTX helpers ----------------
#define FFMA2(c, a, b) asm("fma.rn.f32x2 %0, %1, %2, %0;" : "+l"(c) : "l"(a), "l"(b))
#define PACK2(o, lo, hi) asm("mov.b64 %0, {%1, %2};" : "=l"(o) : "f"(lo), "f"(hi))
#define UNPACK2(lo, hi, i) asm("mov.b64 {%0, %1}, %2;" : "=f"(lo), "=f"(hi) : "l"(i))

// bit-cast helpers (register renames only)
__device__ __forceinline__ unsigned int h2_as_u(__half2 h) {
    union { __half2 h; unsigned int u; } c; c.h = h; return c.u;
}
__device__ __forceinline__ __half2 u_as_h2(unsigned int u) {
    union { unsigned int u; __half2 h; } c; c.u = u; return c.h;
}

// ---------------- scratch (static device globals; no allocs allowed) ----------------
__device__ uint4 g_linS[NN * 8];    // fp16 dinv-scaled GEMM output: NN x 128 halves
__device__ float g_h[NN * DD];      // post-activation features (fp32, GEMM input)
__device__ int   g_row[EE];
__device__ int   g_col[EE];
__device__ int   g_batch[NN];
__device__ int   g_deg[NN];
__device__ float g_dinv[NN];
__device__ int   g_off[NN + 1];
__device__ int   g_cursor[NN];
__device__ int   g_csr[EE];
__device__ int   g_bsum[256];
__device__ float g_stats[2 * DD];   // [0:128) sum, [128:256) sumsq
__device__ float g_scale[DD];
__device__ float g_shift[DD];
__device__ float g_Wp[DD * DD];     // scale-folded weights
__device__ float g_rvec[DD];        // shift @ W
__device__ float g_pool[GG * DD];
__device__ float g_cnt[GG];
__device__ int   g_is32;

__device__ __forceinline__ float lrelu(float x) { return x > 0.f ? x : 0.01f * x; }

// ---------------- setup: zero buffers + detect index width ----------------
__global__ void k_init(const void* ei) {
    int i = blockIdx.x * blockDim.x + threadIdx.x;
    if (i < NN) g_deg[i] = 0;
    if (i < GG * DD) g_pool[i] = 0.f;
    if (i < GG) g_cnt[i] = 0.f;
    if (i < 2 * DD) g_stats[i] = 0.f;
    if (blockIdx.x == 0) {
        // int32 data read as int64 pairs gives values out of [0, NN) w.h.p.
        __shared__ int bad;
        if (threadIdx.x == 0) bad = 0;
        __syncthreads();
        const long long* p = (const long long*)ei;
        for (int j = threadIdx.x; j < 4096; j += blockDim.x) {
            long long v = p[j];
            if (v < 0 || v >= NN) bad = 1;
        }
        __syncthreads();
        if (threadIdx.x == 0) g_is32 = bad;
    }
}

// convert indices + degree histogram + batch convert + graph-size histogram
__global__ void k_convert_all(const void* ei, const void* bidx) {
    int e = blockIdx.x * blockDim.x + threadIdx.x;
    int is32 = g_is32;
    if (e < EE) {
        int r, c;
        if (is32) {
            const int* p = (const int*)ei;
            r = p[e]; c = p[EE + e];
        } else {
            const long long* p = (const long long*)ei;
            r = (int)p[e]; c = (int)p[EE + e];
        }
        g_row[e] = r;
        g_col[e] = c;
        atomicAdd(&g_deg[c], 1);
    }
    if (e < NN) {
        int b = is32 ? ((const int*)bidx)[e] : (int)((const long long*)bidx)[e];
        g_batch[e] = b;
        atomicAdd(&g_cnt[b], 1.0f);
    }
}

// ---------------- exclusive scan of deg -> off ----------------
__global__ void k_scanA() {
    __shared__ int s[256];
    int b = blockIdx.x, t = threadIdx.x;
    int base = b * 512 + t * 2;
    int v0 = (base < NN) ? g_deg[base] : 0;
    int v1 = (base + 1 < NN) ? g_deg[base + 1] : 0;
    int tsum = v0 + v1;
    s[t] = tsum;
    __syncthreads();
    int val = tsum;
    for (int d = 1; d < 256; d <<= 1) {
        int o = (t >= d) ? s[t - d] : 0;
        __syncthreads();
        val += o;
        s[t] = val;
        __syncthreads();
    }
    int excl = val - tsum;
    if (base < NN) g_off[base] = excl;
    if (base + 1 < NN) g_off[base + 1] = excl + v0;
    if (t == 255) g_bsum[b] = val;
}

__global__ void k_scanB() {
    __shared__ int s[256];
    int t = threadIdx.x;
    int v = g_bsum[t];
    s[t] = v;
    __syncthreads();
    int val = v;
    for (int d = 1; d < 256; d <<= 1) {
        int o = (t >= d) ? s[t - d] : 0;
        __syncthreads();
        val += o;
        s[t] = val;
        __syncthreads();
    }
    g_bsum[t] = val - v;
}

// scan finalize + dinv
__global__ void k_scanC() {
    int i = blockIdx.x * blockDim.x + threadIdx.x;
    if (i < NN) {
        int o = g_off[i] + g_bsum[i >> 9];
        g_off[i] = o;
        g_cursor[i] = o;
        g_dinv[i] = rsqrtf((float)g_deg[i] + 1.0f);
    }
    if (i == 0) g_off[NN] = EE;
}

__global__ void k_scatter() {
    int e = blockIdx.x * blockDim.x + threadIdx.x;
    if (e < EE) {
        int c = g_col[e];
        int slot = atomicAdd(&g_cursor[c], 1);
        g_csr[slot] = g_row[e];
    }
}

// ---------------- layer 0 GEMM: linS = fp16( dinv * (x[N,9] @ W0[9,128]) ) ----------------
__global__ void __launch_bounds__(256) k_gemm0(const float* __restrict__ x,
                                               const float* __restrict__ W0) {
    __shared__ float Ws[9 * DD];
    for (int i = threadIdx.x; i < 9 * DD; i += blockDim.x) Ws[i] = W0[i];
    __syncthreads();
    int gid = blockIdx.x * blockDim.x + threadIdx.x;
    if (gid >= NN * DD) return;
    int i = gid >> 7, f = gid & 127;
    float s = 0.f;
#pragma unroll
    for (int k = 0; k < 9; k++) s += x[i * 9 + k] * Ws[k * DD + f];
    ((__half*)g_linS)[gid] = __float2half_rn(g_dinv[i] * s);
}

// ---------------- BN prep: stats -> scale/shift, then reset stats ----------------
__global__ void k_bnprep(const float* __restrict__ gam, const float* __restrict__ bet) {
    int f = threadIdx.x;
    if (f < DD) {
        float m = g_stats[f] * (1.0f / NN);
        float v = g_stats[DD + f] * (1.0f / NN) - m * m;
        float sc = gam[f] * rsqrtf(fmaxf(v, 0.f) + BN_EPS);
        g_scale[f] = sc;
        g_shift[f] = bet[f] - m * sc;
        g_stats[f] = 0.f;
        g_stats[DD + f] = 0.f;
    }
}

// ---------------- weight prep: Wp = diag(scale) W ; rvec = shift @ W ----------------
__global__ void __launch_bounds__(256) k_wprep(const float* __restrict__ W) {
    if (blockIdx.x < 64) {
        int idx = blockIdx.x * 256 + threadIdx.x;     // 0..16383
        int k = idx >> 7;
        g_Wp[idx] = g_scale[k] * W[idx];
    } else {
        int n = threadIdx.x;
        if (n < DD) {
            float s = 0.f;
#pragma unroll 8
            for (int k = 0; k < DD; k++) s += g_shift[k] * W[k * DD + n];
            g_rvec[n] = s;
        }
    }
}

// ---------------- main GEMM: linS = fp16( dinv * (h @ Wp + rvec) ), f32x2 microkernel ----------------
__global__ void __launch_bounds__(256) k_gemm128() {
    __shared__ float As[2][16][132];
    __shared__ float Bs[2][16][128];
    int row0 = blockIdx.x * 128;
    int tid = threadIdx.x;
    int tr = tid >> 4, tc = tid & 15;

    unsigned long long acc2[8][4] = {};    // 8 m-rows x 4 n-pairs

    const float4* A4 = (const float4*)g_h;
    const float4* W4 = (const float4*)g_Wp;

    float4 la0, la1, lb0, lb1;
    int slot0 = tid * 2, slot1 = tid * 2 + 1;
    int ar0 = slot0 >> 2, akq0 = slot0 & 3;
    int ar1 = slot1 >> 2, akq1 = slot1 & 3;
    int bk0 = slot0 >> 5, bn0 = slot0 & 31;
    int bk1 = slot1 >> 5, bn1 = slot1 & 31;
    int grow0 = row0 + ar0, grow1 = row0 + ar1;
    bool ok0 = grow0 < NN, ok1 = grow1 < NN;

#define LOADREGS(kt)                                                        \
    {                                                                       \
        la0 = ok0 ? A4[grow0 * 32 + (kt) * 4 + akq0]                        \
                  : make_float4(0.f, 0.f, 0.f, 0.f);                        \
        la1 = ok1 ? A4[grow1 * 32 + (kt) * 4 + akq1]                        \
                  : make_float4(0.f, 0.f, 0.f, 0.f);                        \
        lb0 = W4[((kt) * 16 + bk0) * 32 + bn0];                             \
        lb1 = W4[((kt) * 16 + bk1) * 32 + bn1];                             \
    }

#define STORESMEM(buf)                                                      \
    {                                                                       \
        As[buf][akq0 * 4 + 0][ar0] = la0.x;                                 \
        As[buf][akq0 * 4 + 1][ar0] = la0.y;                                 \
        As[buf][akq0 * 4 + 2][ar0] = la0.z;                                 \
        As[buf][akq0 * 4 + 3][ar0] = la0.w;                                 \
        As[buf][akq1 * 4 + 0][ar1] = la1.x;                                 \
        As[buf][akq1 * 4 + 1][ar1] = la1.y;                                 \
        As[buf][akq1 * 4 + 2][ar1] = la1.z;                                 \
        As[buf][akq1 * 4 + 3][ar1] = la1.w;                                 \
        *(float4*)&Bs[buf][bk0][bn0 * 4] = lb0;                             \
        *(float4*)&Bs[buf][bk1][bn1 * 4] = lb1;                             \
    }

    LOADREGS(0);
    STORESMEM(0);
    __syncthreads();

    for (int kt = 0; kt < 8; kt++) {
        int buf = kt & 1;
        if (kt < 7) LOADREGS(kt + 1);
#pragma unroll
        for (int kk = 0; kk < 16; kk++) {
            float4 a0 = *(const float4*)&As[buf][kk][tr * 8];
            float4 a1 = *(const float4*)&As[buf][kk][tr * 8 + 4];
            ulonglong2 bb0 = *(const ulonglong2*)&Bs[buf][kk][tc * 8];
            ulonglong2 bb1 = *(const ulonglong2*)&Bs[buf][kk][tc * 8 + 4];
            unsigned long long bp0 = bb0.x, bp1 = bb0.y, bp2 = bb1.x, bp3 = bb1.y;
            float av[8] = {a0.x, a0.y, a0.z, a0.w, a1.x, a1.y, a1.z, a1.w};
#pragma unroll
            for (int m = 0; m < 8; m++) {
                unsigned long long am2;
                PACK2(am2, av[m], av[m]);
                FFMA2(acc2[m][0], am2, bp0);
                FFMA2(acc2[m][1], am2, bp1);
                FFMA2(acc2[m][2], am2, bp2);
                FFMA2(acc2[m][3], am2, bp3);
            }
        }
        if (kt < 7) STORESMEM((kt + 1) & 1);
        __syncthreads();
    }
#undef LOADREGS
#undef STORESMEM

    // epilogue: out = fp16( dinv * (acc + rvec) ), 8 halves = one 16B store
    const float* rv = &g_rvec[tc * 8];
    float r0 = rv[0], r1 = rv[1], r2 = rv[2], r3 = rv[3];
    float r4 = rv[4], r5 = rv[5], r6 = rv[6], r7 = rv[7];
#pragma unroll
    for (int m = 0; m < 8; m++) {
        int row = row0 + tr * 8 + m;
        if (row < NN) {
            float d = g_dinv[row];
            float c0, c1, c2, c3, c4, c5, c6, c7;
            UNPACK2(c0, c1, acc2[m][0]);
            UNPACK2(c2, c3, acc2[m][1]);
            UNPACK2(c4, c5, acc2[m][2]);
            UNPACK2(c6, c7, acc2[m][3]);
            __half2 p0 = __floats2half2_rn(d * (c0 + r0), d * (c1 + r1));
            __half2 p1 = __floats2half2_rn(d * (c2 + r2), d * (c3 + r3));
            __half2 p2 = __floats2half2_rn(d * (c4 + r4), d * (c5 + r5));
            __half2 p3 = __floats2half2_rn(d * (c6 + r6), d * (c7 + r7));
            uint4 st;
            st.x = h2_as_u(p0);
            st.y = h2_as_u(p1);
            st.z = h2_as_u(p2);
            st.w = h2_as_u(p3);
            g_linS[row * 16 + tc] = st;
        }
    }
}

// ---------------- SpMM: warp per destination node, fp16 gathers ----------------
template <bool FINAL>
__global__ void __launch_bounds__(256) k_spmm(const float* __restrict__ bias) {
    __shared__ float ssum[DD], ssq[DD];
    int tid = threadIdx.x;
    if (!FINAL) {
        for (int i = tid; i < DD; i += blockDim.x) { ssum[i] = 0.f; ssq[i] = 0.f; }
        __syncthreads();
    }
    int lane = tid & 31;
    int gw = (blockIdx.x * blockDim.x + tid) >> 5;
    int nw = (gridDim.x * blockDim.x) >> 5;
    const uint2* lin2 = (const uint2*)g_linS;   // 32 uint2 (= 4 halves each) per row
    float4 b4 = ((const float4*)bias)[lane];
    float s0 = 0, s1 = 0, s2 = 0, s3 = 0, q0 = 0, q1 = 0, q2 = 0, q3 = 0;

    for (int i = gw; i < NN; i += nw) {
        int e0 = g_off[i], e1 = g_off[i + 1];
        float ax = 0.f, ay = 0.f, az = 0.f, aw = 0.f;
        int e = e0;
        for (; e + 4 <= e1; e += 4) {
            int r0 = g_csr[e], r1 = g_csr[e + 1], r2 = g_csr[e + 2], r3 = g_csr[e + 3];
            uint2 v0 = lin2[r0 * 32 + lane];
            uint2 v1 = lin2[r1 * 32 + lane];
            uint2 v2 = lin2[r2 * 32 + lane];
            uint2 v3 = lin2[r3 * 32 + lane];
            float2 f;
            f = __half22float2(u_as_h2(v0.x)); ax += f.x; ay += f.y;
            f = __half22float2(u_as_h2(v0.y)); az += f.x; aw += f.y;
            f = __half22float2(u_as_h2(v1.x)); ax += f.x; ay += f.y;
            f = __half22float2(u_as_h2(v1.y)); az += f.x; aw += f.y;
            f = __half22float2(u_as_h2(v2.x)); ax += f.x; ay += f.y;
            f = __half22float2(u_as_h2(v2.y)); az += f.x; aw += f.y;
            f = __half22float2(u_as_h2(v3.x)); ax += f.x; ay += f.y;
            f = __half22float2(u_as_h2(v3.y)); az += f.x; aw += f.y;
        }
        for (; e < e1; e++) {
            int r = g_csr[e];
            uint2 v = lin2[r * 32 + lane];
            float2 f;
            f = __half22float2(u_as_h2(v.x)); ax += f.x; ay += f.y;
            f = __half22float2(u_as_h2(v.y)); az += f.x; aw += f.y;
        }
        uint2 sv = lin2[i * 32 + lane];
        {
            float2 f;
            f = __half22float2(u_as_h2(sv.x)); ax += f.x; ay += f.y;
            f = __half22float2(u_as_h2(sv.y)); az += f.x; aw += f.y;
        }
        float di = g_dinv[i];
        float hx = lrelu(fmaf(di, ax, b4.x));
        float hy = lrelu(fmaf(di, ay, b4.y));
        float hz = lrelu(fmaf(di, az, b4.z));
        float hw = lrelu(fmaf(di, aw, b4.w));
        if (!FINAL) {
            ((float4*)g_h)[i * 32 + lane] = make_float4(hx, hy, hz, hw);
            s0 += hx; s1 += hy; s2 += hz; s3 += hw;
            q0 += hx * hx; q1 += hy * hy; q2 += hz * hz; q3 += hw * hw;
        } else {
            int bi = g_batch[i];
            float* p = &g_pool[bi * DD + lane * 4];
            atomicAdd(p + 0, hx);
            atomicAdd(p + 1, hy);
            atomicAdd(p + 2, hz);
            atomicAdd(p + 3, hw);
        }
    }

    if (!FINAL) {
        atomicAdd(&ssum[lane * 4 + 0], s0);
        atomicAdd(&ssum[lane * 4 + 1], s1);
        atomicAdd(&ssum[lane * 4 + 2], s2);
        atomicAdd(&ssum[lane * 4 + 3], s3);
        atomicAdd(&ssq[lane * 4 + 0], q0);
        atomicAdd(&ssq[lane * 4 + 1], q1);
        atomicAdd(&ssq[lane * 4 + 2], q2);
        atomicAdd(&ssq[lane * 4 + 3], q3);
        __syncthreads();
        for (int i = tid; i < DD; i += blockDim.x) {
            atomicAdd(&g_stats[i], ssum[i]);
            atomicAdd(&g_stats[DD + i], ssq[i]);
        }
    }
}

// ---------------- output head: warp per graph ----------------
__global__ void k_out(const float* __restrict__ Wout, const float* __restrict__ bout,
                      float* __restrict__ out) {
    int t = blockIdx.x * blockDim.x + threadIdx.x;
    int w = t >> 5, lane = t & 31;
    if (w >= GG) return;
    float4 p = ((const float4*)g_pool)[w * 32 + lane];
    float4 wv = ((const float4*)Wout)[lane];
    float d = p.x * wv.x + p.y * wv.y + p.z * wv.z + p.w * wv.w;
#pragma unroll
    for (int o = 16; o; o >>= 1) d += __shfl_down_sync(0xffffffffu, d, o);
    if (lane == 0) {
        float c = fmaxf(g_cnt[w], 1.0f);
        out[w] = d / c + bout[0];
    }
}

// ---------------- launch ----------------
extern "C" void kernel_launch(void* const* d_in, const int* in_sizes, int n_in,
                              void* d_out, int out_size) {
    const float* x     = (const float*)d_in[0];
    const void*  ei    = d_in[1];
    const void*  bidx  = d_in[2];
    const float* W0    = (const float*)d_in[3];
    const float* b0    = (const float*)d_in[4];
    const float* W1    = (const float*)d_in[5];
    const float* b1    = (const float*)d_in[6];
    const float* W2    = (const float*)d_in[7];
    const float* b2    = (const float*)d_in[8];
    const float* W3    = (const float*)d_in[9];
    const float* b3    = (const float*)d_in[10];
    const float* g1    = (const float*)d_in[11];
    const float* be1   = (const float*)d_in[12];
    const float* g2    = (const float*)d_in[13];
    const float* be2   = (const float*)d_in[14];
    const float* g3    = (const float*)d_in[15];
    const float* be3   = (const float*)d_in[16];
    const float* Wout  = (const float*)d_in[17];
    const float* bout  = (const float*)d_in[18];
    float* out = (float*)d_out;

    const int EB = (EE + 255) / 256;     // 6250
    const int NB = (NN + 255) / 256;     // 391
    const int GB = (NN + 127) / 128;     // 782
    const int SPMM_BLOCKS = 888;

    // preprocessing
    k_init<<<(GG * DD + 255) / 256, 256>>>(ei);
    k_convert_all<<<EB, 256>>>(ei, bidx);
    k_scanA<<<256, 256>>>();
    k_scanB<<<1, 256>>>();
    k_scanC<<<NB, 256>>>();
    k_scatter<<<EB, 256>>>();

    // layer 0 (K=9)
    k_gemm0<<<(NN * DD) / 256, 256>>>(x, W0);
    k_spmm<false><<<SPMM_BLOCKS, 256>>>(b0);

    // layer 1
    k_bnprep<<<1, 128>>>(g1, be1);
    k_wprep<<<65, 256>>>(W1);
    k_gemm128<<<GB, 256>>>();
    k_spmm<false><<<SPMM_BLOCKS, 256>>>(b1);

    // layer 2
    k_bnprep<<<1, 128>>>(g2, be2);
    k_wprep<<<65, 256>>>(W2);
    k_gemm128<<<GB, 256>>>();
    k_spmm<false><<<SPMM_BLOCKS, 256>>>(b2);

    // layer 3 (final, fused pooling)
    k_bnprep<<<1, 128>>>(g3, be3);
    k_wprep<<<65, 256>>>(W3);
    k_gemm128<<<GB, 256>>>();
    k_spmm<true><<<SPMM_BLOCKS, 256>>>(b3);

    // head
    k_out<<<(GG * 32 + 255) / 256, 256>>>(Wout, bout, out);

    (void)in_sizes; (void)n_in; (void)out_size;
}

// round 5
// speedup vs baseline: 1.6288x; 1.3810x over previous
#include <cuda_runtime.h>
#include <cuda_fp16.h>

#define NN 100000
#define EE 1600000
#define GG 2048
#define DD 128
#define BN_EPS 1e-5f

// bit-cast helpers (register renames only)
__device__ __forceinline__ unsigned int h2_as_u(__half2 h) {
    union { __half2 h; unsigned int u; } c; c.h = h; return c.u;
}
__device__ __forceinline__ __half2 u_as_h2(unsigned int u) {
    union { unsigned int u; __half2 h; } c; c.u = u; return c.h;
}

// ---------------- scratch (static device globals; no allocs allowed) ----------------
__device__ uint4  g_linS[NN * 8];    // fp16 dinv-scaled GEMM output: NN x 128 halves
__device__ __half g_hh[NN * DD];     // post-activation features (fp16, GEMM A input)
__device__ int    g_row[EE];
__device__ int    g_col[EE];
__device__ int    g_batch[NN];
__device__ int    g_deg[NN];
__device__ float  g_dinv[NN];
__device__ int    g_off[NN + 1];
__device__ int    g_cursor[NN];
__device__ int    g_csr[EE];
__device__ int    g_bsum[256];
__device__ float  g_stats[2 * DD];   // [0:128) sum, [128:256) sumsq
__device__ float  g_scale[DD];
__device__ float  g_shift[DD];
__device__ __half g_Wph[DD * DD];    // scale-folded weights, n-major (transposed), fp16
__device__ float  g_rvec[DD];        // shift @ W
__device__ float  g_pool[GG * DD];
__device__ float  g_cnt[GG];
__device__ int    g_is32;

__device__ __forceinline__ float lrelu(float x) { return x > 0.f ? x : 0.01f * x; }

// ---------------- setup: zero buffers + detect index width ----------------
__global__ void k_init(const void* ei) {
    int i = blockIdx.x * blockDim.x + threadIdx.x;
    if (i < NN) g_deg[i] = 0;
    if (i < GG * DD) g_pool[i] = 0.f;
    if (i < GG) g_cnt[i] = 0.f;
    if (i < 2 * DD) g_stats[i] = 0.f;
    if (blockIdx.x == 0) {
        // int32 data read as int64 pairs gives values out of [0, NN) w.h.p.
        __shared__ int bad;
        if (threadIdx.x == 0) bad = 0;
        __syncthreads();
        const long long* p = (const long long*)ei;
        for (int j = threadIdx.x; j < 4096; j += blockDim.x) {
            long long v = p[j];
            if (v < 0 || v >= NN) bad = 1;
        }
        __syncthreads();
        if (threadIdx.x == 0) g_is32 = bad;
    }
}

// convert indices + degree histogram + batch convert + graph-size histogram
__global__ void k_convert_all(const void* ei, const void* bidx) {
    int e = blockIdx.x * blockDim.x + threadIdx.x;
    int is32 = g_is32;
    if (e < EE) {
        int r, c;
        if (is32) {
            const int* p = (const int*)ei;
            r = p[e]; c = p[EE + e];
        } else {
            const long long* p = (const long long*)ei;
            r = (int)p[e]; c = (int)p[EE + e];
        }
        g_row[e] = r;
        g_col[e] = c;
        atomicAdd(&g_deg[c], 1);
    }
    if (e < NN) {
        int b = is32 ? ((const int*)bidx)[e] : (int)((const long long*)bidx)[e];
        g_batch[e] = b;
        atomicAdd(&g_cnt[b], 1.0f);
    }
}

// ---------------- exclusive scan of deg -> off ----------------
__global__ void k_scanA() {
    __shared__ int s[256];
    int b = blockIdx.x, t = threadIdx.x;
    int base = b * 512 + t * 2;
    int v0 = (base < NN) ? g_deg[base] : 0;
    int v1 = (base + 1 < NN) ? g_deg[base + 1] : 0;
    int tsum = v0 + v1;
    s[t] = tsum;
    __syncthreads();
    int val = tsum;
    for (int d = 1; d < 256; d <<= 1) {
        int o = (t >= d) ? s[t - d] : 0;
        __syncthreads();
        val += o;
        s[t] = val;
        __syncthreads();
    }
    int excl = val - tsum;
    if (base < NN) g_off[base] = excl;
    if (base + 1 < NN) g_off[base + 1] = excl + v0;
    if (t == 255) g_bsum[b] = val;
}

__global__ void k_scanB() {
    __shared__ int s[256];
    int t = threadIdx.x;
    int v = g_bsum[t];
    s[t] = v;
    __syncthreads();
    int val = v;
    for (int d = 1; d < 256; d <<= 1) {
        int o = (t >= d) ? s[t - d] : 0;
        __syncthreads();
        val += o;
        s[t] = val;
        __syncthreads();
    }
    g_bsum[t] = val - v;
}

// scan finalize + dinv
__global__ void k_scanC() {
    int i = blockIdx.x * blockDim.x + threadIdx.x;
    if (i < NN) {
        int o = g_off[i] + g_bsum[i >> 9];
        g_off[i] = o;
        g_cursor[i] = o;
        g_dinv[i] = rsqrtf((float)g_deg[i] + 1.0f);
    }
    if (i == 0) g_off[NN] = EE;
}

__global__ void k_scatter() {
    int e = blockIdx.x * blockDim.x + threadIdx.x;
    if (e < EE) {
        int c = g_col[e];
        int slot = atomicAdd(&g_cursor[c], 1);
        g_csr[slot] = g_row[e];
    }
}

// ---------------- layer 0 GEMM: linS = fp16( dinv * (x[N,9] @ W0[9,128]) ) ----------------
__global__ void __launch_bounds__(256) k_gemm0(const float* __restrict__ x,
                                               const float* __restrict__ W0) {
    __shared__ float Ws[9 * DD];
    for (int i = threadIdx.x; i < 9 * DD; i += blockDim.x) Ws[i] = W0[i];
    __syncthreads();
    int gid = blockIdx.x * blockDim.x + threadIdx.x;
    if (gid >= NN * DD) return;
    int i = gid >> 7, f = gid & 127;
    float s = 0.f;
#pragma unroll
    for (int k = 0; k < 9; k++) s += x[i * 9 + k] * Ws[k * DD + f];
    ((__half*)g_linS)[gid] = __float2half_rn(g_dinv[i] * s);
}

// ---------------- BN prep: stats -> scale/shift, then reset stats ----------------
__global__ void k_bnprep(const float* __restrict__ gam, const float* __restrict__ bet) {
    int f = threadIdx.x;
    if (f < DD) {
        float m = g_stats[f] * (1.0f / NN);
        float v = g_stats[DD + f] * (1.0f / NN) - m * m;
        float sc = gam[f] * rsqrtf(fmaxf(v, 0.f) + BN_EPS);
        g_scale[f] = sc;
        g_shift[f] = bet[f] - m * sc;
        g_stats[f] = 0.f;
        g_stats[DD + f] = 0.f;
    }
}

// ---------------- weight prep: Wph[n][k] = fp16(scale[k]*W[k][n]) ; rvec = shift @ W ----------------
__global__ void __launch_bounds__(256) k_wprep(const float* __restrict__ W) {
    if (blockIdx.x < 64) {
        int idx = blockIdx.x * 256 + threadIdx.x;     // 0..16383, = k*128+n
        int k = idx >> 7, n = idx & 127;
        g_Wph[n * DD + k] = __float2half(g_scale[k] * W[idx]);
    } else {
        int n = threadIdx.x;
        if (n < DD) {
            float s = 0.f;
#pragma unroll 8
            for (int k = 0; k < DD; k++) s += g_shift[k] * W[k * DD + n];
            g_rvec[n] = s;
        }
    }
}

// ---------------- main GEMM (HMMA): linS = fp16( dinv * (h @ Wp + rvec) ) ----------------
// 256 threads = 8 warps; each warp computes a 16x128 tile via mma.m16n8k16.
__global__ void __launch_bounds__(256) k_gemm128() {
    __shared__ __half Bs[DD][136];    // n-major, padded: bank = (4n+qp)%32, conflict-free
    int tid = threadIdx.x;
    // load Wph (n-major) into smem, 8 halves per 16B
    for (int idx = tid * 8; idx < DD * DD; idx += 256 * 8) {
        uint4 v = *(const uint4*)&g_Wph[idx];
        int n = idx >> 7, k = idx & 127;
        *(uint4*)&Bs[n][k] = v;
    }
    __syncthreads();

    int wid = tid >> 5, lane = tid & 31;
    int qr = lane >> 2, qp = lane & 3;
    int rowbase = blockIdx.x * 128 + wid * 16;
    int r0 = rowbase + qr, r1 = rowbase + qr + 8;
    bool ok0 = r0 < NN, ok1 = r1 < NN;
    const unsigned* A0 = (const unsigned*)(g_hh + (size_t)r0 * DD);
    const unsigned* A1 = (const unsigned*)(g_hh + (size_t)r1 * DD);

    float acc[16][4];
#pragma unroll
    for (int nt = 0; nt < 16; nt++)
#pragma unroll
        for (int j = 0; j < 4; j++) acc[nt][j] = 0.f;

#pragma unroll
    for (int kt = 0; kt < 8; kt++) {
        int k0 = kt * 16;
        unsigned a0 = 0, a1 = 0, a2 = 0, a3 = 0;
        if (ok0) { a0 = A0[k0 / 2 + qp]; a2 = A0[k0 / 2 + 4 + qp]; }
        if (ok1) { a1 = A1[k0 / 2 + qp]; a3 = A1[k0 / 2 + 4 + qp]; }
#pragma unroll
        for (int nt = 0; nt < 16; nt++) {
            int n = nt * 8 + qr;
            unsigned b0 = *(const unsigned*)&Bs[n][k0 + qp * 2];
            unsigned b1 = *(const unsigned*)&Bs[n][k0 + 8 + qp * 2];
            asm volatile(
                "mma.sync.aligned.m16n8k16.row.col.f32.f16.f16.f32 "
                "{%0,%1,%2,%3}, {%4,%5,%6,%7}, {%8,%9}, {%0,%1,%2,%3};"
                : "+f"(acc[nt][0]), "+f"(acc[nt][1]), "+f"(acc[nt][2]), "+f"(acc[nt][3])
                : "r"(a0), "r"(a1), "r"(a2), "r"(a3), "r"(b0), "r"(b1));
        }
    }

    // epilogue: linS = fp16( dinv * (acc + rvec) )
    float d0 = ok0 ? g_dinv[r0] : 0.f;
    float d1 = ok1 ? g_dinv[r1] : 0.f;
    unsigned* o0 = (unsigned*)((__half*)g_linS + (size_t)r0 * DD);
    unsigned* o1 = (unsigned*)((__half*)g_linS + (size_t)r1 * DD);
#pragma unroll
    for (int nt = 0; nt < 16; nt++) {
        int n = nt * 8 + qp * 2;
        float rv0 = g_rvec[n], rv1 = g_rvec[n + 1];
        if (ok0) {
            __half2 p = __floats2half2_rn(d0 * (acc[nt][0] + rv0), d0 * (acc[nt][1] + rv1));
            o0[n / 2] = h2_as_u(p);
        }
        if (ok1) {
            __half2 p = __floats2half2_rn(d1 * (acc[nt][2] + rv0), d1 * (acc[nt][3] + rv1));
            o1[n / 2] = h2_as_u(p);
        }
    }
}

// ---------------- SpMM: warp per destination node, fp16 gathers ----------------
template <bool FINAL>
__global__ void __launch_bounds__(256) k_spmm(const float* __restrict__ bias) {
    __shared__ float ssum[DD], ssq[DD];
    int tid = threadIdx.x;
    if (!FINAL) {
        for (int i = tid; i < DD; i += blockDim.x) { ssum[i] = 0.f; ssq[i] = 0.f; }
        __syncthreads();
    }
    int lane = tid & 31;
    int gw = (blockIdx.x * blockDim.x + tid) >> 5;
    int nw = (gridDim.x * blockDim.x) >> 5;
    const uint2* lin2 = (const uint2*)g_linS;   // 32 uint2 (= 4 halves each) per row
    float4 b4 = ((const float4*)bias)[lane];
    float s0 = 0, s1 = 0, s2 = 0, s3 = 0, q0 = 0, q1 = 0, q2 = 0, q3 = 0;

    for (int i = gw; i < NN; i += nw) {
        int e0 = g_off[i], e1 = g_off[i + 1];
        float ax = 0.f, ay = 0.f, az = 0.f, aw = 0.f;
        int e = e0;
        for (; e + 4 <= e1; e += 4) {
            int r0 = g_csr[e], r1 = g_csr[e + 1], r2 = g_csr[e + 2], r3 = g_csr[e + 3];
            uint2 v0 = lin2[r0 * 32 + lane];
            uint2 v1 = lin2[r1 * 32 + lane];
            uint2 v2 = lin2[r2 * 32 + lane];
            uint2 v3 = lin2[r3 * 32 + lane];
            float2 f;
            f = __half22float2(u_as_h2(v0.x)); ax += f.x; ay += f.y;
            f = __half22float2(u_as_h2(v0.y)); az += f.x; aw += f.y;
            f = __half22float2(u_as_h2(v1.x)); ax += f.x; ay += f.y;
            f = __half22float2(u_as_h2(v1.y)); az += f.x; aw += f.y;
            f = __half22float2(u_as_h2(v2.x)); ax += f.x; ay += f.y;
            f = __half22float2(u_as_h2(v2.y)); az += f.x; aw += f.y;
            f = __half22float2(u_as_h2(v3.x)); ax += f.x; ay += f.y;
            f = __half22float2(u_as_h2(v3.y)); az += f.x; aw += f.y;
        }
        for (; e < e1; e++) {
            int r = g_csr[e];
            uint2 v = lin2[r * 32 + lane];
            float2 f;
            f = __half22float2(u_as_h2(v.x)); ax += f.x; ay += f.y;
            f = __half22float2(u_as_h2(v.y)); az += f.x; aw += f.y;
        }
        uint2 sv = lin2[i * 32 + lane];
        {
            float2 f;
            f = __half22float2(u_as_h2(sv.x)); ax += f.x; ay += f.y;
            f = __half22float2(u_as_h2(sv.y)); az += f.x; aw += f.y;
        }
        float di = g_dinv[i];
        float hx = lrelu(fmaf(di, ax, b4.x));
        float hy = lrelu(fmaf(di, ay, b4.y));
        float hz = lrelu(fmaf(di, az, b4.z));
        float hw = lrelu(fmaf(di, aw, b4.w));
        if (!FINAL) {
            uint2 st;
            st.x = h2_as_u(__floats2half2_rn(hx, hy));
            st.y = h2_as_u(__floats2half2_rn(hz, hw));
            ((uint2*)g_hh)[i * 32 + lane] = st;
            s0 += hx; s1 += hy; s2 += hz; s3 += hw;
            q0 += hx * hx; q1 += hy * hy; q2 += hz * hz; q3 += hw * hw;
        } else {
            int bi = g_batch[i];
            float* p = &g_pool[bi * DD + lane * 4];
            atomicAdd(p + 0, hx);
            atomicAdd(p + 1, hy);
            atomicAdd(p + 2, hz);
            atomicAdd(p + 3, hw);
        }
    }

    if (!FINAL) {
        atomicAdd(&ssum[lane * 4 + 0], s0);
        atomicAdd(&ssum[lane * 4 + 1], s1);
        atomicAdd(&ssum[lane * 4 + 2], s2);
        atomicAdd(&ssum[lane * 4 + 3], s3);
        atomicAdd(&ssq[lane * 4 + 0], q0);
        atomicAdd(&ssq[lane * 4 + 1], q1);
        atomicAdd(&ssq[lane * 4 + 2], q2);
        atomicAdd(&ssq[lane * 4 + 3], q3);
        __syncthreads();
        for (int i = tid; i < DD; i += blockDim.x) {
            atomicAdd(&g_stats[i], ssum[i]);
            atomicAdd(&g_stats[DD + i], ssq[i]);
        }
    }
}

// ---------------- output head: warp per graph ----------------
__global__ void k_out(const float* __restrict__ Wout, const float* __restrict__ bout,
                      float* __restrict__ out) {
    int t = blockIdx.x * blockDim.x + threadIdx.x;
    int w = t >> 5, lane = t & 31;
    if (w >= GG) return;
    float4 p = ((const float4*)g_pool)[w * 32 + lane];
    float4 wv = ((const float4*)Wout)[lane];
    float d = p.x * wv.x + p.y * wv.y + p.z * wv.z + p.w * wv.w;
#pragma unroll
    for (int o = 16; o; o >>= 1) d += __shfl_down_sync(0xffffffffu, d, o);
    if (lane == 0) {
        float c = fmaxf(g_cnt[w], 1.0f);
        out[w] = d / c + bout[0];
    }
}

// ---------------- launch ----------------
extern "C" void kernel_launch(void* const* d_in, const int* in_sizes, int n_in,
                              void* d_out, int out_size) {
    const float* x     = (const float*)d_in[0];
    const void*  ei    = d_in[1];
    const void*  bidx  = d_in[2];
    const float* W0    = (const float*)d_in[3];
    const float* b0    = (const float*)d_in[4];
    const float* W1    = (const float*)d_in[5];
    const float* b1    = (const float*)d_in[6];
    const float* W2    = (const float*)d_in[7];
    const float* b2    = (const float*)d_in[8];
    const float* W3    = (const float*)d_in[9];
    const float* b3    = (const float*)d_in[10];
    const float* g1    = (const float*)d_in[11];
    const float* be1   = (const float*)d_in[12];
    const float* g2    = (const float*)d_in[13];
    const float* be2   = (const float*)d_in[14];
    const float* g3    = (const float*)d_in[15];
    const float* be3   = (const float*)d_in[16];
    const float* Wout  = (const float*)d_in[17];
    const float* bout  = (const float*)d_in[18];
    float* out = (float*)d_out;

    const int EB = (EE + 255) / 256;     // 6250
    const int NB = (NN + 255) / 256;     // 391
    const int GB = (NN + 127) / 128;     // 782
    const int SPMM_BLOCKS = 888;

    // preprocessing
    k_init<<<(GG * DD + 255) / 256, 256>>>(ei);
    k_convert_all<<<EB, 256>>>(ei, bidx);
    k_scanA<<<256, 256>>>();
    k_scanB<<<1, 256>>>();
    k_scanC<<<NB, 256>>>();
    k_scatter<<<EB, 256>>>();

    // layer 0 (K=9)
    k_gemm0<<<(NN * DD) / 256, 256>>>(x, W0);
    k_spmm<false><<<SPMM_BLOCKS, 256>>>(b0);

    // layer 1
    k_bnprep<<<1, 128>>>(g1, be1);
    k_wprep<<<65, 256>>>(W1);
    k_gemm128<<<GB, 256>>>();
    k_spmm<false><<<SPMM_BLOCKS, 256>>>(b1);

    // layer 2
    k_bnprep<<<1, 128>>>(g2, be2);
    k_wprep<<<65, 256>>>(W2);
    k_gemm128<<<GB, 256>>>();
    k_spmm<false><<<SPMM_BLOCKS, 256>>>(b2);

    // layer 3 (final, fused pooling)
    k_bnprep<<<1, 128>>>(g3, be3);
    k_wprep<<<65, 256>>>(W3);
    k_gemm128<<<GB, 256>>>();
    k_spmm<true><<<SPMM_BLOCKS, 256>>>(b3);

    // head
    k_out<<<(GG * 32 + 255) / 256, 256>>>(Wout, bout, out);

    (void)in_sizes; (void)n_in; (void)out_size;
}